// round 7
// baseline (speedup 1.0000x reference)
#include <cuda_runtime.h>

#define LOG2PI_F 1.8378770664093454f   // log(2*pi)
#define LOG2E_F  1.4426950408889634f   // log2(e)

typedef unsigned long long u64;

__device__ __forceinline__ u64 pack2(float lo, float hi) {
    u64 r; asm("mov.b64 %0, {%1, %2};" : "=l"(r) : "f"(lo), "f"(hi)); return r;
}
__device__ __forceinline__ void unpack2(u64 v, float& lo, float& hi) {
    asm("mov.b64 {%0, %1}, %2;" : "=f"(lo), "=f"(hi) : "l"(v));
}
__device__ __forceinline__ u64 add2(u64 a, u64 b) {
    u64 r; asm("add.rn.f32x2 %0, %1, %2;" : "=l"(r) : "l"(a), "l"(b)); return r;
}
__device__ __forceinline__ u64 mul2(u64 a, u64 b) {
    u64 r; asm("mul.rn.f32x2 %0, %1, %2;" : "=l"(r) : "l"(a), "l"(b)); return r;
}
__device__ __forceinline__ u64 fma2(u64 a, u64 b, u64 c) {
    u64 r; asm("fma.rn.f32x2 %0, %1, %2, %3;" : "=l"(r) : "l"(a), "l"(b), "l"(c)); return r;
}

// Each thread handles FOUR batch points (b, b+Q, b+2Q, b+3Q with Q=B/4) for
// one keypoint k, as two independent f32x2-packed chains (X: b,b+2Q / Y: b+Q,b+3Q).
// Grid is (B/4/128, K) = 1024 blocks -> a SINGLE wave on 148 SMs (8 blocks/SM).
// Params are loaded from smem once per component and feed both chains.
__global__ __launch_bounds__(128, 8)
void recovery_policy_kernel(
    const float* __restrict__ z,      // [B,K,2]
    const float* __restrict__ w,      // [K,C]
    const float* __restrict__ mu,     // [K,C,2]
    const float* __restrict__ cov,    // [K,C,2,2]
    const float* __restrict__ scale,  // [K,2]
    float* __restrict__ out,
    int B, int K, int C, int gradOff)
{
    const int k   = blockIdx.y;
    const int tid = threadIdx.x;

    // splatted packed params: sA = {(i00,i00),(i01,i01)}, sB = {(i11,i11),(c2,c2)},
    // sM = {(-m0,-m0),(-m1,-m1)}
    __shared__ ulonglong2 sA[64];
    __shared__ ulonglong2 sB[64];
    __shared__ ulonglong2 sM[64];
    __shared__ float2 s_scale;

    if (tid < C) {
        const int idx = k * C + tid;
        const float4 cv = ((const float4*)cov)[idx];     // a b c d
        const float det  = cv.x * cv.w - cv.y * cv.z;
        const float rdet = 1.0f / det;
        const float i00 =  cv.w * rdet;
        const float i01 = -cv.y * rdet;
        const float i11 =  cv.x * rdet;
        const float c2  = (logf(w[idx]) - 0.5f * logf(det) - LOG2PI_F) * LOG2E_F;
        const float2 m  = ((const float2*)mu)[idx];
        sA[tid] = make_ulonglong2(pack2(i00, i00), pack2(i01, i01));
        sB[tid] = make_ulonglong2(pack2(i11, i11), pack2(c2, c2));
        sM[tid] = make_ulonglong2(pack2(-m.x, -m.x), pack2(-m.y, -m.y));
    }
    if (tid == 0) s_scale = ((const float2*)scale)[k];
    __syncthreads();

    const int Q = B >> 2;
    const int b0 = blockIdx.x * blockDim.x + tid;
    if (b0 >= Q) return;
    const int b1 = b0 + Q;
    const int b2 = b0 + 2 * Q;
    const int b3 = b0 + 3 * Q;

    const float2 z0 = __ldg(&((const float2*)z)[(size_t)b0 * K + k]);
    const float2 z1 = __ldg(&((const float2*)z)[(size_t)b1 * K + k]);
    const float2 z2 = __ldg(&((const float2*)z)[(size_t)b2 * K + k]);
    const float2 z3 = __ldg(&((const float2*)z)[(size_t)b3 * K + k]);

    // chain X packs (b0, b2); chain Y packs (b1, b3)
    const u64 zx0 = pack2(z0.x, z2.x);
    const u64 zx1 = pack2(z0.y, z2.y);
    const u64 zy0 = pack2(z1.x, z3.x);
    const u64 zy1 = pack2(z1.y, z3.y);

    const float nh = -0.5f * LOG2E_F;
    const u64 nhp = pack2(nh, nh);

    u64 pdfX = 0ULL, g0X = 0ULL, g1X = 0ULL;
    u64 pdfY = 0ULL, g0Y = 0ULL, g1Y = 0ULL;

    #pragma unroll 8
    for (int c = 0; c < C; c++) {
        const ulonglong2 A  = sA[c];
        const ulonglong2 Bv = sB[c];
        const ulonglong2 M  = sM[c];
        // chain X
        {
            const u64 d0 = add2(zx0, M.x);
            const u64 d1 = add2(zx1, M.y);
            const u64 s0 = fma2(A.x, d0, mul2(A.y, d1));
            const u64 s1 = fma2(A.y, d0, mul2(Bv.x, d1));
            const u64 maha = fma2(d0, s0, mul2(d1, s1));
            const u64 arg  = fma2(maha, nhp, Bv.y);
            float aLo, aHi; unpack2(arg, aLo, aHi);
            const u64 ep = pack2(exp2f(aLo), exp2f(aHi));
            pdfX = add2(pdfX, ep);
            g0X  = fma2(ep, s0, g0X);
            g1X  = fma2(ep, s1, g1X);
        }
        // chain Y
        {
            const u64 d0 = add2(zy0, M.x);
            const u64 d1 = add2(zy1, M.y);
            const u64 s0 = fma2(A.x, d0, mul2(A.y, d1));
            const u64 s1 = fma2(A.y, d0, mul2(Bv.x, d1));
            const u64 maha = fma2(d0, s0, mul2(d1, s1));
            const u64 arg  = fma2(maha, nhp, Bv.y);
            float aLo, aHi; unpack2(arg, aLo, aHi);
            const u64 ep = pack2(exp2f(aLo), exp2f(aHi));
            pdfY = add2(pdfY, ep);
            g0Y  = fma2(ep, s0, g0Y);
            g1Y  = fma2(ep, s1, g1Y);
        }
    }

    const float sx = s_scale.x, sy = s_scale.y;

    float pdfA, pdfB, gA0, gB0, gA1, gB1;

    // epilogue helper (macro-ish via lambda)
    auto finish = [&](float pdf, float gg0, float gg1, int b) {
        const float gx = -gg0 * sx, gy = -gg1 * sy;
        const float dn = 1.0f / (1.0f + expf(1.0f - 2.0f * pdf));
        const float nrm = sqrtf(gx * gx + gy * gy);
        const float mag = expf((5500.0f - nrm) * (1.0f / 1100.0f));
        const float r = mag / nrm;
        ((float2*)out)[(size_t)b * K + k] = make_float2(dn, dn);
        ((float2*)(out + gradOff))[(size_t)b * K + k] = make_float2(gx * r, gy * r);
    };

    unpack2(pdfX, pdfA, pdfB);
    unpack2(g0X,  gA0,  gB0);
    unpack2(g1X,  gA1,  gB1);
    finish(pdfA, gA0, gA1, b0);
    finish(pdfB, gB0, gB1, b2);

    unpack2(pdfY, pdfA, pdfB);
    unpack2(g0Y,  gA0,  gB0);
    unpack2(g1Y,  gA1,  gB1);
    finish(pdfA, gA0, gA1, b1);
    finish(pdfB, gB0, gB1, b3);
}

extern "C" void kernel_launch(void* const* d_in, const int* in_sizes, int n_in,
                              void* d_out, int out_size)
{
    const float* z     = (const float*)d_in[0];  // [B,K,2]
    const float* w     = (const float*)d_in[1];  // [K,C]
    const float* mu    = (const float*)d_in[2];  // [K,C,2]
    const float* cov   = (const float*)d_in[3];  // [K,C,2,2]
    const float* scale = (const float*)d_in[4];  // [K,2]
    float* out = (float*)d_out;

    const int K = in_sizes[4] / 2;
    const int C = in_sizes[1] / K;
    const int B = in_sizes[0] / (2 * K);
    const int gradOff = out_size / 2;

    const int Q = B / 4;
    dim3 grid((Q + 127) / 128, K);
    recovery_policy_kernel<<<grid, 128>>>(z, w, mu, cov, scale, out,
                                          B, K, C, gradOff);
}

// round 9
// speedup vs baseline: 1.2854x; 1.2854x over previous
#include <cuda_runtime.h>

#define LOG2PI_F 1.8378770664093454f   // log(2*pi)
#define LOG2E_F  1.4426950408889634f   // log2(e)
#define LN2_F    0.6931471805599453f   // ln(2)

// arg_c(z) = A z0^2 + B z0 z1 + C z1^2 + D z0 + E z1 + F   (base-2 exponent)
// comp_c   = 2^{arg_c}
// pdf      = sum_c comp_c
// -sum comp*s0 = ln2 * (2 z0 * Se A + z1 * Se B + Se D)
// -sum comp*s1 = ln2 * (z0 * Se B + 2 z1 * Se C + Se E)
__global__ __launch_bounds__(128)
void recovery_policy_kernel(
    const float* __restrict__ z,      // [B,K,2]
    const float* __restrict__ w,      // [K,C]
    const float* __restrict__ mu,     // [K,C,2]
    const float* __restrict__ cov,    // [K,C,2,2]
    const float* __restrict__ scale,  // [K,2]
    float* __restrict__ out,
    int B, int K, int C, int gradOff)
{
    const int k   = blockIdx.y;
    const int tid = threadIdx.x;

    __shared__ float4 sP[64];   // A, B, C, D
    __shared__ float2 sQ[64];   // E, F
    __shared__ float2 s_scale;

    if (tid < C) {
        const int idx = k * C + tid;
        const float4 cv = ((const float4*)cov)[idx];      // a b c d (2x2 row-major)
        const float det  = cv.x * cv.w - cv.y * cv.z;
        const float rdet = 1.0f / det;
        const float i00 =  cv.w * rdet;
        const float i01 = -cv.y * rdet;
        const float i11 =  cv.x * rdet;
        const float2 m  = ((const float2*)mu)[idx];
        const float c2  = (logf(w[idx]) - 0.5f * logf(det) - LOG2PI_F) * LOG2E_F;
        const float nh  = -0.5f * LOG2E_F;
        const float u0  = i00 * m.x + i01 * m.y;          // (Sigma^-1 mu)_0
        const float u1  = i01 * m.x + i11 * m.y;          // (Sigma^-1 mu)_1
        const float A  = nh * i00;
        const float Bc = nh * 2.0f * i01;
        const float Cc = nh * i11;
        const float D  = -2.0f * nh * u0;
        const float E  = -2.0f * nh * u1;
        const float F  = nh * (m.x * u0 + m.y * u1) + c2;
        sP[tid] = make_float4(A, Bc, Cc, D);
        sQ[tid] = make_float2(E, F);
    }
    if (tid == 0) s_scale = ((const float2*)scale)[k];
    __syncthreads();

    const int b = blockIdx.x * blockDim.x + tid;
    if (b >= B) return;

    const float2 zz = __ldg(&((const float2*)z)[(size_t)b * K + k]);
    const float z0 = zz.x, z1 = zz.y;
    const float m00 = z0 * z0;     // z0^2
    const float m01 = z0 * z1;     // z0*z1
    const float m11 = z1 * z1;     // z1^2

    float P  = 0.0f;
    float aA = 0.0f, aB = 0.0f, aC = 0.0f, aD = 0.0f, aE = 0.0f;

    #pragma unroll 8
    for (int c = 0; c < C; c++) {
        const float4 p = sP[c];
        const float2 q = sQ[c];
        float t = fmaf(p.x, m00, q.y);
        t = fmaf(p.y, m01, t);
        t = fmaf(p.z, m11, t);
        t = fmaf(p.w, z0,  t);
        t = fmaf(q.x, z1,  t);
        const float e = exp2f(t);
        P  += e;
        aA = fmaf(e, p.x, aA);
        aB = fmaf(e, p.y, aB);
        aC = fmaf(e, p.z, aC);
        aD = fmaf(e, p.w, aD);
        aE = fmaf(e, q.x, aE);
    }

    // gradient of pdf wrt z (already negated), rescaled into raw latent space
    const float gx = LN2_F * fmaf(2.0f * z0, aA, fmaf(z1, aB, aD)) * s_scale.x;
    const float gy = LN2_F * fmaf(2.0f * z1, aC, fmaf(z0, aB, aE)) * s_scale.y;

    // density_norm = sigmoid((pdf - 0.5)/0.5) = 1/(1 + exp(1 - 2 pdf))
    const float dn = 1.0f / (1.0f + expf(1.0f - 2.0f * P));

    const float nrm = sqrtf(gx * gx + gy * gy);
    const float mag = expf((5500.0f - nrm) * (1.0f / 1100.0f));
    const float r   = mag / nrm;

    ((float2*)out)[(size_t)b * K + k] = make_float2(dn, dn);
    ((float2*)(out + gradOff))[(size_t)b * K + k] = make_float2(gx * r, gy * r);
}

extern "C" void kernel_launch(void* const* d_in, const int* in_sizes, int n_in,
                              void* d_out, int out_size)
{
    const float* z     = (const float*)d_in[0];  // [B,K,2]
    const float* w     = (const float*)d_in[1];  // [K,C]
    const float* mu    = (const float*)d_in[2];  // [K,C,2]
    const float* cov   = (const float*)d_in[3];  // [K,C,2,2]
    const float* scale = (const float*)d_in[4];  // [K,2]
    float* out = (float*)d_out;

    const int K = in_sizes[4] / 2;
    const int C = in_sizes[1] / K;
    const int B = in_sizes[0] / (2 * K);
    const int gradOff = out_size / 2;

    dim3 grid((B + 127) / 128, K);
    recovery_policy_kernel<<<grid, 128>>>(z, w, mu, cov, scale, out,
                                          B, K, C, gradOff);
}

// round 13
// speedup vs baseline: 1.3763x; 1.0707x over previous
#include <cuda_runtime.h>

#define LOG2PI_F 1.8378770664093454f   // log(2*pi)
#define LOG2E_F  1.4426950408889634f   // log2(e)
#define LN2_F    0.6931471805599453f   // ln(2)

// arg_c(z) = A z0^2 + B z0 z1 + C z1^2 + D z0 + E z1 + F   (base-2 exponent)
// comp_c   = 2^{arg_c};  pdf = sum_c comp_c
// grad0 = ln2 * (2 z0 * SeA + z1 * SeB + SeD)   (already the signed pdf-gradient)
// grad1 = ln2 * (z0 * SeB + 2 z1 * SeC + SeE)
// Each thread: TWO batch points (b, b+B/2), sharing every shared-mem param load.
__global__ __launch_bounds__(64)
void recovery_policy_kernel(
    const float* __restrict__ z,      // [B,K,2]
    const float* __restrict__ w,      // [K,C]
    const float* __restrict__ mu,     // [K,C,2]
    const float* __restrict__ cov,    // [K,C,2,2]
    const float* __restrict__ scale,  // [K,2]
    float* __restrict__ out,
    int B, int K, int C, int gradOff)
{
    const int k   = blockIdx.y;
    const int tid = threadIdx.x;

    __shared__ float4 sP[64];   // A, B, C, D
    __shared__ float2 sQ[64];   // E, F
    __shared__ float2 s_scale;

    if (tid < C) {
        const int idx = k * C + tid;
        const float4 cv = ((const float4*)cov)[idx];      // a b c d (2x2 row-major)
        const float det  = cv.x * cv.w - cv.y * cv.z;
        const float rdet = 1.0f / det;
        const float i00 =  cv.w * rdet;
        const float i01 = -cv.y * rdet;
        const float i11 =  cv.x * rdet;
        const float2 m  = ((const float2*)mu)[idx];
        const float c2  = (logf(w[idx]) - 0.5f * logf(det) - LOG2PI_F) * LOG2E_F;
        const float nh  = -0.5f * LOG2E_F;
        const float u0  = i00 * m.x + i01 * m.y;          // (Sigma^-1 mu)_0
        const float u1  = i01 * m.x + i11 * m.y;          // (Sigma^-1 mu)_1
        const float A  = nh * i00;
        const float Bc = nh * 2.0f * i01;
        const float Cc = nh * i11;
        const float D  = -2.0f * nh * u0;
        const float E  = -2.0f * nh * u1;
        const float F  = nh * (m.x * u0 + m.y * u1) + c2;
        sP[tid] = make_float4(A, Bc, Cc, D);
        sQ[tid] = make_float2(E, F);
    }
    if (tid == 0) s_scale = ((const float2*)scale)[k];
    __syncthreads();

    const int halfB = B >> 1;
    const int bX = blockIdx.x * blockDim.x + tid;
    if (bX >= halfB) return;
    const int bY = bX + halfB;

    const float2 zzX = __ldg(&((const float2*)z)[(size_t)bX * K + k]);
    const float2 zzY = __ldg(&((const float2*)z)[(size_t)bY * K + k]);
    const float x0 = zzX.x, x1 = zzX.y;
    const float y0 = zzY.x, y1 = zzY.y;
    const float xm00 = x0 * x0, xm01 = x0 * x1, xm11 = x1 * x1;
    const float ym00 = y0 * y0, ym01 = y0 * y1, ym11 = y1 * y1;

    float PX = 0.0f, xA = 0.0f, xB = 0.0f, xC = 0.0f, xD = 0.0f, xE = 0.0f;
    float PY = 0.0f, yA = 0.0f, yB = 0.0f, yC = 0.0f, yD = 0.0f, yE = 0.0f;

    #pragma unroll 8
    for (int c = 0; c < C; c++) {
        const float4 p = sP[c];
        const float2 q = sQ[c];
        // point X exponent
        float tx = fmaf(p.x, xm00, q.y);
        tx = fmaf(p.y, xm01, tx);
        tx = fmaf(p.z, xm11, tx);
        tx = fmaf(p.w, x0,  tx);
        tx = fmaf(q.x, x1,  tx);
        // point Y exponent
        float ty = fmaf(p.x, ym00, q.y);
        ty = fmaf(p.y, ym01, ty);
        ty = fmaf(p.z, ym11, ty);
        ty = fmaf(p.w, y0,  ty);
        ty = fmaf(q.x, y1,  ty);
        const float ex = exp2f(tx);
        const float ey = exp2f(ty);
        PX += ex;                       PY += ey;
        xA = fmaf(ex, p.x, xA);         yA = fmaf(ey, p.x, yA);
        xB = fmaf(ex, p.y, xB);         yB = fmaf(ey, p.y, yB);
        xC = fmaf(ex, p.z, xC);         yC = fmaf(ey, p.z, yC);
        xD = fmaf(ex, p.w, xD);         yD = fmaf(ey, p.w, yD);
        xE = fmaf(ex, q.x, xE);         yE = fmaf(ey, q.x, yE);
    }

    const float sx = s_scale.x, sy = s_scale.y;

    // point X epilogue
    {
        const float gx = LN2_F * fmaf(2.0f * x0, xA, fmaf(x1, xB, xD)) * sx;
        const float gy = LN2_F * fmaf(2.0f * x1, xC, fmaf(x0, xB, xE)) * sy;
        const float dn = 1.0f / (1.0f + expf(1.0f - 2.0f * PX));
        const float nrm = sqrtf(gx * gx + gy * gy);
        const float mag = expf((5500.0f - nrm) * (1.0f / 1100.0f));
        const float r = mag / nrm;
        ((float2*)out)[(size_t)bX * K + k] = make_float2(dn, dn);
        ((float2*)(out + gradOff))[(size_t)bX * K + k] = make_float2(gx * r, gy * r);
    }
    // point Y epilogue
    {
        const float gx = LN2_F * fmaf(2.0f * y0, yA, fmaf(y1, yB, yD)) * sx;
        const float gy = LN2_F * fmaf(2.0f * y1, yC, fmaf(y0, yB, yE)) * sy;
        const float dn = 1.0f / (1.0f + expf(1.0f - 2.0f * PY));
        const float nrm = sqrtf(gx * gx + gy * gy);
        const float mag = expf((5500.0f - nrm) * (1.0f / 1100.0f));
        const float r = mag / nrm;
        ((float2*)out)[(size_t)bY * K + k] = make_float2(dn, dn);
        ((float2*)(out + gradOff))[(size_t)bY * K + k] = make_float2(gx * r, gy * r);
    }
}

extern "C" void kernel_launch(void* const* d_in, const int* in_sizes, int n_in,
                              void* d_out, int out_size)
{
    const float* z     = (const float*)d_in[0];  // [B,K,2]
    const float* w     = (const float*)d_in[1];  // [K,C]
    const float* mu    = (const float*)d_in[2];  // [K,C,2]
    const float* cov   = (const float*)d_in[3];  // [K,C,2,2]
    const float* scale = (const float*)d_in[4];  // [K,2]
    float* out = (float*)d_out;

    const int K = in_sizes[4] / 2;
    const int C = in_sizes[1] / K;
    const int B = in_sizes[0] / (2 * K);
    const int gradOff = out_size / 2;

    const int halfB = B / 2;
    dim3 grid((halfB + 63) / 64, K);
    recovery_policy_kernel<<<grid, 64>>>(z, w, mu, cov, scale, out,
                                         B, K, C, gradOff);
}

// round 15
// speedup vs baseline: 1.5139x; 1.1000x over previous
#include <cuda_runtime.h>

#define LOG2PI_F 1.8378770664093454f   // log(2*pi)
#define LOG2E_F  1.4426950408889634f   // log2(e)
#define LN2_F    0.6931471805599453f   // ln(2)

__device__ __forceinline__ float ex2_fast(float x) {
    float r;
    asm("ex2.approx.ftz.f32 %0, %1;" : "=f"(r) : "f"(x));
    return r;
}

// arg_c(z) = A z0^2 + B z0 z1 + C z1^2 + D z0 + E z1 + F   (base-2 exponent)
// comp_c   = 2^{arg_c};  pdf = sum_c comp_c
// grad0 = ln2 * (2 z0 * SeA + z1 * SeB + SeD)   (signed pdf-gradient)
// grad1 = ln2 * (z0 * SeB + 2 z1 * SeC + SeE)
// Each thread: TWO batch points (b, b+B/2), sharing every shared-mem param load.
__global__ __launch_bounds__(64)
void recovery_policy_kernel(
    const float* __restrict__ z,      // [B,K,2]
    const float* __restrict__ w,      // [K,C]
    const float* __restrict__ mu,     // [K,C,2]
    const float* __restrict__ cov,    // [K,C,2,2]
    const float* __restrict__ scale,  // [K,2]
    float* __restrict__ out,
    int B, int K, int C, int gradOff)
{
    const int k   = blockIdx.y;
    const int tid = threadIdx.x;

    __shared__ float4 sP[64];   // A, B, C, D
    __shared__ float2 sQ[64];   // E, F
    __shared__ float2 s_scale;

    if (tid < C) {
        const int idx = k * C + tid;
        const float4 cv = ((const float4*)cov)[idx];      // a b c d (2x2 row-major)
        const float det  = cv.x * cv.w - cv.y * cv.z;
        const float rdet = 1.0f / det;
        const float i00 =  cv.w * rdet;
        const float i01 = -cv.y * rdet;
        const float i11 =  cv.x * rdet;
        const float2 m  = ((const float2*)mu)[idx];
        const float c2  = (logf(w[idx]) - 0.5f * logf(det) - LOG2PI_F) * LOG2E_F;
        const float nh  = -0.5f * LOG2E_F;
        const float u0  = i00 * m.x + i01 * m.y;          // (Sigma^-1 mu)_0
        const float u1  = i01 * m.x + i11 * m.y;          // (Sigma^-1 mu)_1
        const float A  = nh * i00;
        const float Bc = nh * 2.0f * i01;
        const float Cc = nh * i11;
        const float D  = -2.0f * nh * u0;
        const float E  = -2.0f * nh * u1;
        const float F  = nh * (m.x * u0 + m.y * u1) + c2;
        sP[tid] = make_float4(A, Bc, Cc, D);
        sQ[tid] = make_float2(E, F);
    }
    if (tid == 0) s_scale = ((const float2*)scale)[k];
    __syncthreads();

    const int halfB = B >> 1;
    const int bX = blockIdx.x * blockDim.x + tid;
    if (bX >= halfB) return;
    const int bY = bX + halfB;

    const float2 zzX = __ldg(&((const float2*)z)[(size_t)bX * K + k]);
    const float2 zzY = __ldg(&((const float2*)z)[(size_t)bY * K + k]);
    const float x0 = zzX.x, x1 = zzX.y;
    const float y0 = zzY.x, y1 = zzY.y;
    const float xm00 = x0 * x0, xm01 = x0 * x1, xm11 = x1 * x1;
    const float ym00 = y0 * y0, ym01 = y0 * y1, ym11 = y1 * y1;

    float PX = 0.0f, xA = 0.0f, xB = 0.0f, xC = 0.0f, xD = 0.0f, xE = 0.0f;
    float PY = 0.0f, yA = 0.0f, yB = 0.0f, yC = 0.0f, yD = 0.0f, yE = 0.0f;

    #pragma unroll 8
    for (int c = 0; c < C; c++) {
        const float4 p = sP[c];
        const float2 q = sQ[c];
        // point X exponent
        float tx = fmaf(p.x, xm00, q.y);
        tx = fmaf(p.y, xm01, tx);
        tx = fmaf(p.z, xm11, tx);
        tx = fmaf(p.w, x0,  tx);
        tx = fmaf(q.x, x1,  tx);
        // point Y exponent
        float ty = fmaf(p.x, ym00, q.y);
        ty = fmaf(p.y, ym01, ty);
        ty = fmaf(p.z, ym11, ty);
        ty = fmaf(p.w, y0,  ty);
        ty = fmaf(q.x, y1,  ty);
        const float ex = ex2_fast(tx);
        const float ey = ex2_fast(ty);
        PX += ex;                       PY += ey;
        xA = fmaf(ex, p.x, xA);         yA = fmaf(ey, p.x, yA);
        xB = fmaf(ex, p.y, xB);         yB = fmaf(ey, p.y, yB);
        xC = fmaf(ex, p.z, xC);         yC = fmaf(ey, p.z, yC);
        xD = fmaf(ex, p.w, xD);         yD = fmaf(ey, p.w, yD);
        xE = fmaf(ex, q.x, xE);         yE = fmaf(ey, q.x, yE);
    }

    const float sx = s_scale.x, sy = s_scale.y;

    // point X epilogue
    {
        const float gx = LN2_F * fmaf(2.0f * x0, xA, fmaf(x1, xB, xD)) * sx;
        const float gy = LN2_F * fmaf(2.0f * x1, xC, fmaf(x0, xB, xE)) * sy;
        // sigmoid(2P-1) = 1/(1 + 2^{(1-2P)·log2e})
        const float dn = 1.0f / (1.0f + ex2_fast((1.0f - 2.0f * PX) * LOG2E_F));
        const float nrm = sqrtf(gx * gx + gy * gy);
        const float mag = ex2_fast((5500.0f - nrm) * (LOG2E_F / 1100.0f));
        const float r = mag / nrm;
        ((float2*)out)[(size_t)bX * K + k] = make_float2(dn, dn);
        ((float2*)(out + gradOff))[(size_t)bX * K + k] = make_float2(gx * r, gy * r);
    }
    // point Y epilogue
    {
        const float gx = LN2_F * fmaf(2.0f * y0, yA, fmaf(y1, yB, yD)) * sx;
        const float gy = LN2_F * fmaf(2.0f * y1, yC, fmaf(y0, yB, yE)) * sy;
        const float dn = 1.0f / (1.0f + ex2_fast((1.0f - 2.0f * PY) * LOG2E_F));
        const float nrm = sqrtf(gx * gx + gy * gy);
        const float mag = ex2_fast((5500.0f - nrm) * (LOG2E_F / 1100.0f));
        const float r = mag / nrm;
        ((float2*)out)[(size_t)bY * K + k] = make_float2(dn, dn);
        ((float2*)(out + gradOff))[(size_t)bY * K + k] = make_float2(gx * r, gy * r);
    }
}

extern "C" void kernel_launch(void* const* d_in, const int* in_sizes, int n_in,
                              void* d_out, int out_size)
{
    const float* z     = (const float*)d_in[0];  // [B,K,2]
    const float* w     = (const float*)d_in[1];  // [K,C]
    const float* mu    = (const float*)d_in[2];  // [K,C,2]
    const float* cov   = (const float*)d_in[3];  // [K,C,2,2]
    const float* scale = (const float*)d_in[4];  // [K,2]
    float* out = (float*)d_out;

    const int K = in_sizes[4] / 2;
    const int C = in_sizes[1] / K;
    const int B = in_sizes[0] / (2 * K);
    const int gradOff = out_size / 2;

    const int halfB = B / 2;
    dim3 grid((halfB + 63) / 64, K);
    recovery_policy_kernel<<<grid, 64>>>(z, w, mu, cov, scale, out,
                                         B, K, C, gradOff);
}